// round 16
// baseline (speedup 1.0000x reference)
#include <cuda_runtime.h>
#include <cuda_fp16.h>
#include <cstdint>

#define NN 100000
#define EE 1600000
#define INCH 128
#define HID 64
#define OUTC 40
#define ELLW 64   // max degree capacity; Poisson(16) -> P(deg>=64) ~ e^-40, safe

#define G1_BLOCKS ((NN + 127) / 128)   // 782
#define SC_BLOCKS 768
#define SP 136    // smem stride (halves) for W1^T tiles (conflict-free B-fragment LDS)
#define SP2 72    // smem stride (halves) for W2^T tiles (bank = 4g+t, conflict-free)

// ---------------- scratch (device globals; no allocation allowed) ----------------
// NOTE: self-cleaning state machine — g_cnt and g_dbin are zero at launch start
// (zero-initialized at load; re-zeroed by agg2 / scan65 each launch) so the
// kernel sequence is replay-deterministic under CUDA graph capture.
__device__ int     g_cnt[NN];
__device__ __align__(16) int g_adj[(size_t)NN * ELLW + 16];
__device__ float   g_dinv[NN];
__device__ __align__(16) __half g_xw[(size_t)NN * HID];   // dinv[r] * (x @ W1)[r]
__device__ __align__(16) __half g_h1[(size_t)NN * HID];   // relu(agg1), fp16
__device__ __align__(16) __half g_h2[(size_t)NN * OUTC];  // dinv[r] * (h1 @ W2)[r]
__device__ int     g_dbin[65];    // degree histogram (re-zeroed by scan65)
__device__ int     g_dcur[65];    // degree-class cursors (rewritten each launch)
__device__ int     g_perm[NN];    // degree-sorted node order

// ---------------- HMMA m16n8k16 (row.col, f16 in, f32 acc) ----------------
__device__ __forceinline__ void mma16816(float* d, const unsigned* a, unsigned b0, unsigned b1) {
    asm volatile(
        "mma.sync.aligned.m16n8k16.row.col.f32.f16.f16.f32 "
        "{%0,%1,%2,%3}, {%4,%5,%6,%7}, {%8,%9}, {%0,%1,%2,%3};"
        : "+f"(d[0]), "+f"(d[1]), "+f"(d[2]), "+f"(d[3])
        : "r"(a[0]), "r"(a[1]), "r"(a[2]), "r"(a[3]), "r"(b0), "r"(b1));
}

// split float2 -> hi half2 + lo (residual) half2
__device__ __forceinline__ void split_f2(float2 f, unsigned& hi, unsigned& lo) {
    __half2 h = __floats2half2_rn(f.x, f.y);
    float2 hf = __half22float2(h);
    __half2 l = __floats2half2_rn(f.x - hf.x, f.y - hf.y);
    hi = *(unsigned*)&h;
    lo = *(unsigned*)&l;
}

// ---------------- fused: tensor-core GEMM1 (blocks [0,782)) + ELL scatter ----------------
// GEMM1: g_xw[N,64](fp16, UNSCALED) = x[N,128] @ W1[128,64]
__global__ __launch_bounds__(256) void fused_g1_scatter_kernel(
    const float* __restrict__ A, const float* __restrict__ W, const void* __restrict__ ei) {
    __shared__ __half Wh[64 * SP];
    __shared__ __half Wl[64 * SP];

    int bx = blockIdx.x;
    if (bx >= G1_BLOCKS) {
        // ---- scatter path: per-block dtype sniff (init_kernel removed) ----
        __shared__ int s_is64;
        if (threadIdx.x == 0) {
            const unsigned int* w = (const unsigned int*)ei;
            int v = 1;
#pragma unroll
            for (int j = 0; j < 64; j++) {
                if (w[2 * j + 1] != 0u) { v = 0; break; }
            }
            s_is64 = v;
        }
        __syncthreads();
        int is64 = s_is64;
        int tid = (bx - G1_BLOCKS) * 256 + threadIdx.x;
        int stride = SC_BLOCKS * 256;
        if (is64) {
            const longlong2* r2 = (const longlong2*)ei;
            const longlong2* c2 = (const longlong2*)((const long long*)ei + EE);
            for (int e = tid; e < EE / 2; e += stride) {
                longlong2 rr = __ldg(&r2[e]);
                longlong2 cc = __ldg(&c2[e]);
                int c0 = (int)cc.x, c1 = (int)cc.y;
                int p0 = atomicAdd(&g_cnt[c0], 1);
                int p1 = atomicAdd(&g_cnt[c1], 1);
                g_adj[(unsigned)c0 * ELLW + p0] = (int)rr.x;
                g_adj[(unsigned)c1 * ELLW + p1] = (int)rr.y;
            }
        } else {
            const int2* r2 = (const int2*)ei;
            const int2* c2 = (const int2*)((const int*)ei + EE);
            for (int e = tid; e < EE / 2; e += stride) {
                int2 rr = __ldg(&r2[e]);
                int2 cc = __ldg(&c2[e]);
                int p0 = atomicAdd(&g_cnt[cc.x], 1);
                int p1 = atomicAdd(&g_cnt[cc.y], 1);
                g_adj[(unsigned)cc.x * ELLW + p0] = rr.x;
                g_adj[(unsigned)cc.y * ELLW + p1] = rr.y;
            }
        }
        return;
    }

    // ---- GEMM path ----
    int tid = threadIdx.x;
    for (int idx = tid; idx < 128 * 64; idx += 256) {
        int k = idx >> 6, n = idx & 63;
        float w = __ldg(&W[idx]);
        __half h = __float2half_rn(w);
        Wh[n * SP + k] = h;
        Wl[n * SP + k] = __float2half_rn(w - __half2float(h));
    }
    __syncthreads();

    int warp = tid >> 5, lane = tid & 31;
    int g = lane >> 2, t = lane & 3;
    int row0 = bx * 128 + warp * 16 + g;    // rows row0 and row0+8
    int ra = (row0 < NN) ? row0 : (NN - 1);
    int rb = (row0 + 8 < NN) ? (row0 + 8) : (NN - 1);
    const float* Ar0 = A + (size_t)ra * 128;
    const float* Ar1 = A + (size_t)rb * 128;

    float d[8][4];
#pragma unroll
    for (int j = 0; j < 8; j++)
#pragma unroll
        for (int q = 0; q < 4; q++) d[j][q] = 0.f;

#pragma unroll
    for (int kk = 0; kk < 8; kk++) {
        int kb = kk * 16 + t * 2;
        float2 L0 = __ldg((const float2*)(Ar0 + kb));
        float2 L1 = __ldg((const float2*)(Ar1 + kb));
        float2 L2 = __ldg((const float2*)(Ar0 + kb + 8));
        float2 L3 = __ldg((const float2*)(Ar1 + kb + 8));
        unsigned ah[4], al[4];
        split_f2(L0, ah[0], al[0]);
        split_f2(L1, ah[1], al[1]);
        split_f2(L2, ah[2], al[2]);
        split_f2(L3, ah[3], al[3]);
#pragma unroll
        for (int j = 0; j < 8; j++) {
            int n = j * 8 + g;
            const __half* ph = &Wh[n * SP + kk * 16 + t * 2];
            const __half* pl = &Wl[n * SP + kk * 16 + t * 2];
            unsigned bh0 = *(const unsigned*)ph;
            unsigned bh1 = *(const unsigned*)(ph + 8);
            unsigned bl0 = *(const unsigned*)pl;
            unsigned bl1 = *(const unsigned*)(pl + 8);
            mma16816(d[j], ah, bh0, bh1);
            mma16816(d[j], ah, bl0, bl1);
            mma16816(d[j], al, bh0, bh1);
        }
    }

#pragma unroll
    for (int j = 0; j < 8; j++) {
        int c0 = j * 8 + t * 2;
        if (row0 < NN) {
            __half2 p = __floats2half2_rn(d[j][0], d[j][1]);
            *(unsigned*)&g_xw[(unsigned)row0 * 64 + c0] = *(unsigned*)&p;
        }
        if (row0 + 8 < NN) {
            __half2 p = __floats2half2_rn(d[j][2], d[j][3]);
            *(unsigned*)&g_xw[(unsigned)(row0 + 8) * 64 + c0] = *(unsigned*)&p;
        }
    }
}

// ---------------- dinv + scale xw + degree histogram ----------------
__global__ void dinv_scale_kernel() {
    unsigned gid = blockIdx.x * blockDim.x + threadIdx.x;
    unsigned node = gid >> 3;
    unsigned lane = gid & 7;
    if (node >= NN) return;
    int cnt = __ldg(&g_cnt[node]);
    float di = rsqrtf((float)(cnt + 1));  // +1 self-loop
    if (lane == 0) {
        g_dinv[node] = di;
        atomicAdd(&g_dbin[cnt > 64 ? 64 : cnt], 1);
    }
    uint4* p = (uint4*)&g_xw[node * 64u + lane * 8u];
    uint4 v = *p;
    __half2* hp = (__half2*)&v;
#pragma unroll
    for (int j = 0; j < 4; j++) {
        float2 f = __half22float2(hp[j]);
        hp[j] = __floats2half2_rn(di * f.x, di * f.y);
    }
    *p = v;
}

// ---------------- scan of 65 degree bins -> cursors (and bin re-zero) ----------------
__global__ void scan65_kernel() {
    __shared__ int s[65];
    int t = threadIdx.x;
    if (t < 65) s[t] = g_dbin[t];
    __syncthreads();
    if (t == 0) {
        int acc = 0;
#pragma unroll
        for (int i = 0; i < 65; i++) { int v = s[i]; s[i] = acc; acc += v; }
    }
    __syncthreads();
    if (t < 65) {
        g_dcur[t] = s[t];
        g_dbin[t] = 0;  // clean for next launch
    }
}

// ---------------- build degree-sorted permutation (block-aggregated counting sort) -------
__global__ void perm_kernel() {
    __shared__ int sbin[65];
    __shared__ int sbase[65];
    int tid = threadIdx.x;
    if (tid < 65) sbin[tid] = 0;
    __syncthreads();
    int node = blockIdx.x * 256 + tid;
    int d = 0, local = 0;
    if (node < NN) {
        d = __ldg(&g_cnt[node]);
        if (d > 64) d = 64;
        local = atomicAdd(&sbin[d], 1);
    }
    __syncthreads();
    if (tid < 65 && sbin[tid] > 0) sbase[tid] = atomicAdd(&g_dcur[tid], sbin[tid]);
    __syncthreads();
    if (node < NN) g_perm[sbase[d] + local] = node;
}

// ---------------- agg helpers ----------------
__device__ __forceinline__ void acc_oct(float* acc,
                                        const uint4& a, const uint4& b,
                                        const uint4& c, const uint4& d,
                                        const uint4& e, const uint4& f,
                                        const uint4& g, const uint4& h) {
    const __half2* pa = (const __half2*)&a;
    const __half2* pb = (const __half2*)&b;
    const __half2* pc = (const __half2*)&c;
    const __half2* pd = (const __half2*)&d;
    const __half2* pe = (const __half2*)&e;
    const __half2* pf = (const __half2*)&f;
    const __half2* pg = (const __half2*)&g;
    const __half2* ph = (const __half2*)&h;
#pragma unroll
    for (int j = 0; j < 4; j++) {
        __half2 s = __hadd2(__hadd2(__hadd2(pa[j], pb[j]), __hadd2(pc[j], pd[j])),
                            __hadd2(__hadd2(pe[j], pf[j]), __hadd2(pg[j], ph[j])));
        float2 fv = __half22float2(s);
        acc[2 * j] += fv.x;
        acc[2 * j + 1] += fv.y;
    }
}
__device__ __forceinline__ void acc_pair(float* acc, const uint4& ua, const uint4& ub) {
    const __half2* pa = (const __half2*)&ua;
    const __half2* pb = (const __half2*)&ub;
#pragma unroll
    for (int j = 0; j < 4; j++) {
        float2 f = __half22float2(__hadd2(pa[j], pb[j]));
        acc[2 * j] += f.x;
        acc[2 * j + 1] += f.y;
    }
}
__device__ __forceinline__ void acc_one(float* acc, const uint4& u) {
    const __half2* p = (const __half2*)&u;
#pragma unroll
    for (int j = 0; j < 4; j++) {
        float2 f = __half22float2(p[j]);
        acc[2 * j] += f.x;
        acc[2 * j + 1] += f.y;
    }
}

// ---------------- agg1: h1 = relu(dinv[c]*(sum_r scaled[r] + scaled[c]) + b1) ----------------
// 8 lanes/node, nodes taken in degree-sorted perm order (warp-mates have ~equal degree).
__global__ void agg1_kernel(const float* __restrict__ b1) {
    unsigned gid = blockIdx.x * blockDim.x + threadIdx.x;
    unsigned nslot = gid >> 3;
    unsigned lane = gid & 7;
    if (nslot >= NN) return;
    unsigned node = (unsigned)__ldg(&g_perm[nslot]);
    const uint4* xw = (const uint4*)g_xw;

    float acc[8];
    {
        uint4 sv = __ldg(&xw[node * 8u + lane]);
        const __half2* hp = (const __half2*)&sv;
#pragma unroll
        for (int j = 0; j < 4; j++) {
            float2 f = __half22float2(hp[j]);
            acc[2 * j] = f.x;
            acc[2 * j + 1] = f.y;
        }
    }

    unsigned s = node * ELLW;
    unsigned e = s + (unsigned)__ldg(&g_cnt[node]);
    unsigned k = s;
    const int4* adj4 = (const int4*)g_adj;
    for (; k + 8 <= e; k += 8) {
        int4 i0 = __ldg(&adj4[k >> 2]);
        int4 i1 = __ldg(&adj4[(k >> 2) + 1]);
        uint4 u0 = __ldg(&xw[(unsigned)i0.x * 8u + lane]);
        uint4 u1 = __ldg(&xw[(unsigned)i0.y * 8u + lane]);
        uint4 u2 = __ldg(&xw[(unsigned)i0.z * 8u + lane]);
        uint4 u3 = __ldg(&xw[(unsigned)i0.w * 8u + lane]);
        uint4 u4 = __ldg(&xw[(unsigned)i1.x * 8u + lane]);
        uint4 u5 = __ldg(&xw[(unsigned)i1.y * 8u + lane]);
        uint4 u6 = __ldg(&xw[(unsigned)i1.z * 8u + lane]);
        uint4 u7 = __ldg(&xw[(unsigned)i1.w * 8u + lane]);
        acc_oct(acc, u0, u1, u2, u3, u4, u5, u6, u7);
    }
    for (; k + 2 <= e; k += 2) {
        int r0 = __ldg(&g_adj[k]);
        int r1 = __ldg(&g_adj[k + 1]);
        uint4 u0 = __ldg(&xw[(unsigned)r0 * 8u + lane]);
        uint4 u1 = __ldg(&xw[(unsigned)r1 * 8u + lane]);
        acc_pair(acc, u0, u1);
    }
    if (k < e) {
        int r = __ldg(&g_adj[k]);
        uint4 u = __ldg(&xw[(unsigned)r * 8u + lane]);
        acc_one(acc, u);
    }

    float di = __ldg(&g_dinv[node]);
    const float4* b14 = (const float4*)b1;
    float4 bb0 = __ldg(&b14[lane * 2]);
    float4 bb1 = __ldg(&b14[lane * 2 + 1]);
    __half2 o[4];
    o[0] = __floats2half2_rn(fmaxf(fmaf(di, acc[0], bb0.x), 0.f),
                             fmaxf(fmaf(di, acc[1], bb0.y), 0.f));
    o[1] = __floats2half2_rn(fmaxf(fmaf(di, acc[2], bb0.z), 0.f),
                             fmaxf(fmaf(di, acc[3], bb0.w), 0.f));
    o[2] = __floats2half2_rn(fmaxf(fmaf(di, acc[4], bb1.x), 0.f),
                             fmaxf(fmaf(di, acc[5], bb1.y), 0.f));
    o[3] = __floats2half2_rn(fmaxf(fmaf(di, acc[6], bb1.z), 0.f),
                             fmaxf(fmaf(di, acc[7], bb1.w), 0.f));
    *(uint4*)&g_h1[node * 64u + lane * 8u] = *(const uint4*)o;
}

// ---------------- GEMM2 (HMMA): g_h2[N,40](fp16) = dinv[row] * (h1(fp16)[N,64] @ W2[64,40]) --
__global__ __launch_bounds__(256) void gemm2_kernel(const float* __restrict__ W) {
    __shared__ __half Wh[40 * SP2];
    __shared__ __half Wl[40 * SP2];
    int tid = threadIdx.x;
    for (int idx = tid; idx < 64 * 40; idx += 256) {
        int k = idx / 40, n = idx - k * 40;
        float w = __ldg(&W[idx]);
        __half h = __float2half_rn(w);
        Wh[n * SP2 + k] = h;
        Wl[n * SP2 + k] = __float2half_rn(w - __half2float(h));
    }
    __syncthreads();

    int warp = tid >> 5, lane = tid & 31;
    int g = lane >> 2, t = lane & 3;
    int row0 = blockIdx.x * 128 + warp * 16 + g;   // rows row0, row0+8
    int ra = (row0 < NN) ? row0 : (NN - 1);
    int rb = (row0 + 8 < NN) ? (row0 + 8) : (NN - 1);
    const __half* H0 = g_h1 + (unsigned)ra * 64;
    const __half* H1 = g_h1 + (unsigned)rb * 64;

    float d[5][4];
#pragma unroll
    for (int j = 0; j < 5; j++)
#pragma unroll
        for (int q = 0; q < 4; q++) d[j][q] = 0.f;

#pragma unroll
    for (int kk = 0; kk < 4; kk++) {
        int kb = kk * 16 + t * 2;
        unsigned a[4];
        a[0] = *(const unsigned*)(H0 + kb);
        a[1] = *(const unsigned*)(H1 + kb);
        a[2] = *(const unsigned*)(H0 + kb + 8);
        a[3] = *(const unsigned*)(H1 + kb + 8);
#pragma unroll
        for (int j = 0; j < 5; j++) {
            int n = j * 8 + g;
            const __half* ph = &Wh[n * SP2 + kk * 16 + t * 2];
            const __half* pl = &Wl[n * SP2 + kk * 16 + t * 2];
            unsigned bh0 = *(const unsigned*)ph;
            unsigned bh1 = *(const unsigned*)(ph + 8);
            unsigned bl0 = *(const unsigned*)pl;
            unsigned bl1 = *(const unsigned*)(pl + 8);
            mma16816(d[j], a, bh0, bh1);
            mma16816(d[j], a, bl0, bl1);
        }
    }

    float di0 = (row0 < NN) ? __ldg(&g_dinv[row0]) : 0.f;
    float di1 = (row0 + 8 < NN) ? __ldg(&g_dinv[row0 + 8]) : 0.f;
#pragma unroll
    for (int j = 0; j < 5; j++) {
        int c0 = j * 8 + t * 2;
        if (row0 < NN) {
            __half2 p = __floats2half2_rn(di0 * d[j][0], di0 * d[j][1]);
            *(unsigned*)&g_h2[(unsigned)row0 * 40 + c0] = *(unsigned*)&p;
        }
        if (row0 + 8 < NN) {
            __half2 p = __floats2half2_rn(di1 * d[j][2], di1 * d[j][3]);
            *(unsigned*)&g_h2[(unsigned)(row0 + 8) * 40 + c0] = *(unsigned*)&p;
        }
    }
}

// ---------------- agg2: out = dinv[c]*(sum_r scaled[r] + scaled[c]) + b2 ----------------
// 5 lanes/node (6 nodes/warp), perm order; zeroes g_cnt after last read (replay-clean).
__global__ void agg2_kernel(const float* __restrict__ b2, float* __restrict__ out) {
    unsigned gtid = blockIdx.x * blockDim.x + threadIdx.x;
    unsigned wid = gtid >> 5;
    unsigned lane = gtid & 31;
    unsigned g = lane / 5;
    unsigned sub = lane - g * 5;
    if (g >= 6) return;
    unsigned nslot = wid * 6 + g;
    if (nslot >= NN) return;
    unsigned node = (unsigned)__ldg(&g_perm[nslot]);
    const uint4* hh = (const uint4*)g_h2;

    float acc[8];
    {
        uint4 sv = __ldg(&hh[node * 5u + sub]);
        const __half2* hp = (const __half2*)&sv;
#pragma unroll
        for (int j = 0; j < 4; j++) {
            float2 f = __half22float2(hp[j]);
            acc[2 * j] = f.x;
            acc[2 * j + 1] = f.y;
        }
    }

    unsigned cnt = (unsigned)__ldg(&g_cnt[node]);
    unsigned s = node * ELLW;
    unsigned e = s + cnt;
    unsigned k = s;
    const int4* adj4 = (const int4*)g_adj;
    for (; k + 8 <= e; k += 8) {
        int4 i0 = __ldg(&adj4[k >> 2]);
        int4 i1 = __ldg(&adj4[(k >> 2) + 1]);
        uint4 u0 = __ldg(&hh[(unsigned)i0.x * 5u + sub]);
        uint4 u1 = __ldg(&hh[(unsigned)i0.y * 5u + sub]);
        uint4 u2 = __ldg(&hh[(unsigned)i0.z * 5u + sub]);
        uint4 u3 = __ldg(&hh[(unsigned)i0.w * 5u + sub]);
        uint4 u4 = __ldg(&hh[(unsigned)i1.x * 5u + sub]);
        uint4 u5 = __ldg(&hh[(unsigned)i1.y * 5u + sub]);
        uint4 u6 = __ldg(&hh[(unsigned)i1.z * 5u + sub]);
        uint4 u7 = __ldg(&hh[(unsigned)i1.w * 5u + sub]);
        acc_oct(acc, u0, u1, u2, u3, u4, u5, u6, u7);
    }
    for (; k + 2 <= e; k += 2) {
        int r0 = __ldg(&g_adj[k]);
        int r1 = __ldg(&g_adj[k + 1]);
        uint4 u0 = __ldg(&hh[(unsigned)r0 * 5u + sub]);
        uint4 u1 = __ldg(&hh[(unsigned)r1 * 5u + sub]);
        acc_pair(acc, u0, u1);
    }
    if (k < e) {
        int r = __ldg(&g_adj[k]);
        uint4 u = __ldg(&hh[(unsigned)r * 5u + sub]);
        acc_one(acc, u);
    }

    float di = __ldg(&g_dinv[node]);
    const float4* b24 = (const float4*)b2;
    float4 bb0 = __ldg(&b24[sub * 2]);
    float4 bb1 = __ldg(&b24[sub * 2 + 1]);
    float4 o0, o1;
    o0.x = fmaf(di, acc[0], bb0.x);
    o0.y = fmaf(di, acc[1], bb0.y);
    o0.z = fmaf(di, acc[2], bb0.z);
    o0.w = fmaf(di, acc[3], bb0.w);
    o1.x = fmaf(di, acc[4], bb1.x);
    o1.y = fmaf(di, acc[5], bb1.y);
    o1.z = fmaf(di, acc[6], bb1.z);
    o1.w = fmaf(di, acc[7], bb1.w);
    float4* dst = (float4*)&out[(unsigned)node * 40 + sub * 8];
    dst[0] = o0;
    dst[1] = o1;

    // self-clean for next graph replay (after all reads of g_cnt in this launch)
    if (sub == 0) g_cnt[node] = 0;
}

// ---------------- launch ----------------
extern "C" void kernel_launch(void* const* d_in, const int* in_sizes, int n_in,
                              void* d_out, int out_size) {
    const float* x  = (const float*)d_in[0];
    const void*  ei = d_in[1];
    const float* W1 = (const float*)d_in[2];
    const float* b1 = (const float*)d_in[3];
    const float* W2 = (const float*)d_in[4];
    const float* b2 = (const float*)d_in[5];
    float* out = (float*)d_out;

    fused_g1_scatter_kernel<<<G1_BLOCKS + SC_BLOCKS, 256>>>(x, W1, ei);
    dinv_scale_kernel<<<(NN * 8 + 255) / 256, 256>>>();
    scan65_kernel<<<1, 128>>>();
    perm_kernel<<<(NN + 255) / 256, 256>>>();
    agg1_kernel<<<(NN * 8 + 255) / 256, 256>>>(b1);
    gemm2_kernel<<<(NN + 127) / 128, 256>>>(W2);
    agg2_kernel<<<(NN + 47) / 48, 256>>>(b2, out);
}

// round 17
// speedup vs baseline: 1.3388x; 1.3388x over previous
#include <cuda_runtime.h>
#include <cuda_fp16.h>
#include <cstdint>

#define NN 100000
#define EE 1600000
#define INCH 128
#define HID 64
#define OUTC 40
#define ELLW 64   // max degree capacity; Poisson(16) -> P(deg>=64) ~ e^-40, safe

#define G1_BLOCKS ((NN + 127) / 128)   // 782
#define SC_BLOCKS 768
#define SP 136    // smem stride (halves) for W1^T tiles (conflict-free B-fragment LDS)
#define SP2 72    // smem stride (halves) for W2^T tiles (bank = 4g+t, conflict-free)
#define SPH 136   // smem stride (halves) for the h1 tile (bank = 4g+t, conflict-free)

// ---------------- scratch (device globals; no allocation allowed) ----------------
__device__ int     g_cnt[NN];
__device__ __align__(16) int g_adj[(size_t)NN * ELLW + 16];
__device__ float   g_dinv[NN];
__device__ __align__(16) __half g_xw[(size_t)NN * HID];   // dinv[r] * (x @ W1)[r]
__device__ __align__(16) __half g_h2[(size_t)NN * OUTC];  // dinv[r] * (h1 @ W2)[r]
__device__ int     g_is64;

// ---------------- HMMA m16n8k16 (row.col, f16 in, f32 acc) ----------------
__device__ __forceinline__ void mma16816(float* d, const unsigned* a, unsigned b0, unsigned b1) {
    asm volatile(
        "mma.sync.aligned.m16n8k16.row.col.f32.f16.f16.f32 "
        "{%0,%1,%2,%3}, {%4,%5,%6,%7}, {%8,%9}, {%0,%1,%2,%3};"
        : "+f"(d[0]), "+f"(d[1]), "+f"(d[2]), "+f"(d[3])
        : "r"(a[0]), "r"(a[1]), "r"(a[2]), "r"(a[3]), "r"(b0), "r"(b1));
}

// split float2 -> hi half2 + lo (residual) half2
__device__ __forceinline__ void split_f2(float2 f, unsigned& hi, unsigned& lo) {
    __half2 h = __floats2half2_rn(f.x, f.y);
    float2 hf = __half22float2(h);
    __half2 l = __floats2half2_rn(f.x - hf.x, f.y - hf.y);
    hi = *(unsigned*)&h;
    lo = *(unsigned*)&l;
}

// ---------------- init: zero counters + dtype sniff (fused) ----------------
__global__ void init_kernel(const void* ei) {
    int i = blockIdx.x * blockDim.x + threadIdx.x;
    if (i < NN) g_cnt[i] = 0;
    if (i == 0) {
        const unsigned int* w = (const unsigned int*)ei;
        int is64 = 1;
        for (int j = 0; j < 64; j++) {
            if (w[2 * j + 1] != 0u) { is64 = 0; break; }
        }
        g_is64 = is64;
    }
}

// ---------------- fused: tensor-core GEMM1 (blocks [0,782)) + ELL scatter ----------------
// GEMM1: g_xw[N,64](fp16, UNSCALED) = x[N,128] @ W1[128,64]
__global__ __launch_bounds__(256) void fused_g1_scatter_kernel(
    const float* __restrict__ A, const float* __restrict__ W, const void* __restrict__ ei) {
    __shared__ __half Wh[64 * SP];
    __shared__ __half Wl[64 * SP];

    int bx = blockIdx.x;
    if (bx >= G1_BLOCKS) {
        // ---- scatter path ----
        int tid = (bx - G1_BLOCKS) * 256 + threadIdx.x;
        int stride = SC_BLOCKS * 256;
        int is64 = g_is64;
        if (is64) {
            const longlong2* r2 = (const longlong2*)ei;
            const longlong2* c2 = (const longlong2*)((const long long*)ei + EE);
            for (int e = tid; e < EE / 2; e += stride) {
                longlong2 rr = __ldg(&r2[e]);
                longlong2 cc = __ldg(&c2[e]);
                int c0 = (int)cc.x, c1 = (int)cc.y;
                int p0 = atomicAdd(&g_cnt[c0], 1);
                int p1 = atomicAdd(&g_cnt[c1], 1);
                g_adj[(unsigned)c0 * ELLW + p0] = (int)rr.x;
                g_adj[(unsigned)c1 * ELLW + p1] = (int)rr.y;
            }
        } else {
            const int2* r2 = (const int2*)ei;
            const int2* c2 = (const int2*)((const int*)ei + EE);
            for (int e = tid; e < EE / 2; e += stride) {
                int2 rr = __ldg(&r2[e]);
                int2 cc = __ldg(&c2[e]);
                int p0 = atomicAdd(&g_cnt[cc.x], 1);
                int p1 = atomicAdd(&g_cnt[cc.y], 1);
                g_adj[(unsigned)cc.x * ELLW + p0] = rr.x;
                g_adj[(unsigned)cc.y * ELLW + p1] = rr.y;
            }
        }
        return;
    }

    // ---- GEMM path ----
    int tid = threadIdx.x;
    for (int idx = tid; idx < 128 * 64; idx += 256) {
        int k = idx >> 6, n = idx & 63;
        float w = __ldg(&W[idx]);
        __half h = __float2half_rn(w);
        Wh[n * SP + k] = h;
        Wl[n * SP + k] = __float2half_rn(w - __half2float(h));
    }
    __syncthreads();

    int warp = tid >> 5, lane = tid & 31;
    int g = lane >> 2, t = lane & 3;
    int row0 = bx * 128 + warp * 16 + g;    // rows row0 and row0+8
    int ra = (row0 < NN) ? row0 : (NN - 1);
    int rb = (row0 + 8 < NN) ? (row0 + 8) : (NN - 1);
    const float* Ar0 = A + (size_t)ra * 128;
    const float* Ar1 = A + (size_t)rb * 128;

    float d[8][4];
#pragma unroll
    for (int j = 0; j < 8; j++)
#pragma unroll
        for (int q = 0; q < 4; q++) d[j][q] = 0.f;

#pragma unroll
    for (int kk = 0; kk < 8; kk++) {
        int kb = kk * 16 + t * 2;
        float2 L0 = __ldg((const float2*)(Ar0 + kb));
        float2 L1 = __ldg((const float2*)(Ar1 + kb));
        float2 L2 = __ldg((const float2*)(Ar0 + kb + 8));
        float2 L3 = __ldg((const float2*)(Ar1 + kb + 8));
        unsigned ah[4], al[4];
        split_f2(L0, ah[0], al[0]);
        split_f2(L1, ah[1], al[1]);
        split_f2(L2, ah[2], al[2]);
        split_f2(L3, ah[3], al[3]);
#pragma unroll
        for (int j = 0; j < 8; j++) {
            int n = j * 8 + g;
            const __half* ph = &Wh[n * SP + kk * 16 + t * 2];
            const __half* pl = &Wl[n * SP + kk * 16 + t * 2];
            unsigned bh0 = *(const unsigned*)ph;
            unsigned bh1 = *(const unsigned*)(ph + 8);
            unsigned bl0 = *(const unsigned*)pl;
            unsigned bl1 = *(const unsigned*)(pl + 8);
            mma16816(d[j], ah, bh0, bh1);
            mma16816(d[j], ah, bl0, bl1);
            mma16816(d[j], al, bh0, bh1);
        }
    }

#pragma unroll
    for (int j = 0; j < 8; j++) {
        int c0 = j * 8 + t * 2;
        if (row0 < NN) {
            __half2 p = __floats2half2_rn(d[j][0], d[j][1]);
            *(unsigned*)&g_xw[(unsigned)row0 * 64 + c0] = *(unsigned*)&p;
        }
        if (row0 + 8 < NN) {
            __half2 p = __floats2half2_rn(d[j][2], d[j][3]);
            *(unsigned*)&g_xw[(unsigned)(row0 + 8) * 64 + c0] = *(unsigned*)&p;
        }
    }
}

// ---------------- dinv + scale xw: di = rsqrt(cnt+1); g_xw *= di ----------------
__global__ void dinv_scale_kernel() {
    unsigned gid = blockIdx.x * blockDim.x + threadIdx.x;
    unsigned node = gid >> 3;
    unsigned lane = gid & 7;
    if (node >= NN) return;
    float di = rsqrtf((float)(__ldg(&g_cnt[node]) + 1));  // +1 self-loop
    if (lane == 0) g_dinv[node] = di;
    uint4* p = (uint4*)&g_xw[node * 64u + lane * 8u];
    uint4 v = *p;
    __half2* hp = (__half2*)&v;
#pragma unroll
    for (int j = 0; j < 4; j++) {
        float2 f = __half22float2(hp[j]);
        hp[j] = __floats2half2_rn(di * f.x, di * f.y);
    }
    *p = v;
}

// ---------------- agg helpers ----------------
__device__ __forceinline__ void acc_oct(float* acc,
                                        const uint4& a, const uint4& b,
                                        const uint4& c, const uint4& d,
                                        const uint4& e, const uint4& f,
                                        const uint4& g, const uint4& h) {
    const __half2* pa = (const __half2*)&a;
    const __half2* pb = (const __half2*)&b;
    const __half2* pc = (const __half2*)&c;
    const __half2* pd = (const __half2*)&d;
    const __half2* pe = (const __half2*)&e;
    const __half2* pf = (const __half2*)&f;
    const __half2* pg = (const __half2*)&g;
    const __half2* ph = (const __half2*)&h;
#pragma unroll
    for (int j = 0; j < 4; j++) {
        __half2 s = __hadd2(__hadd2(__hadd2(pa[j], pb[j]), __hadd2(pc[j], pd[j])),
                            __hadd2(__hadd2(pe[j], pf[j]), __hadd2(pg[j], ph[j])));
        float2 fv = __half22float2(s);
        acc[2 * j] += fv.x;
        acc[2 * j + 1] += fv.y;
    }
}
__device__ __forceinline__ void acc_pair(float* acc, const uint4& ua, const uint4& ub) {
    const __half2* pa = (const __half2*)&ua;
    const __half2* pb = (const __half2*)&ub;
#pragma unroll
    for (int j = 0; j < 4; j++) {
        float2 f = __half22float2(__hadd2(pa[j], pb[j]));
        acc[2 * j] += f.x;
        acc[2 * j + 1] += f.y;
    }
}
__device__ __forceinline__ void acc_one(float* acc, const uint4& u) {
    const __half2* p = (const __half2*)&u;
#pragma unroll
    for (int j = 0; j < 4; j++) {
        float2 f = __half22float2(p[j]);
        acc[2 * j] += f.x;
        acc[2 * j + 1] += f.y;
    }
}

// ---------------- fused agg1 + GEMM2 ----------------
// One block = 128 nodes. Phase 1 (R15 agg1 loop): relu'd h1 -> smem tile (stride SPH=136
// halves: STS.128 and HMMA-fragment LDS both conflict-free, bank = (4g+t)%32).
// Phase 2 (R13 gemm2 HMMA): fragments from smem, dinv-scaled fp16 store to g_h2.
__global__ __launch_bounds__(256) void agg1_gemm2_kernel(const float* __restrict__ b1,
                                                         const float* __restrict__ W) {
    __shared__ __half H1s[128 * SPH];   // 34.8 KB
    __shared__ __half Wh[40 * SP2];     //  5.8 KB
    __shared__ __half Wl[40 * SP2];     //  5.8 KB

    int tid = threadIdx.x;
    // stage W2^T hi/lo
    for (int idx = tid; idx < 64 * 40; idx += 256) {
        int k = idx / 40, n = idx - k * 40;
        float w = __ldg(&W[idx]);
        __half h = __float2half_rn(w);
        Wh[n * SP2 + k] = h;
        Wl[n * SP2 + k] = __float2half_rn(w - __half2float(h));
    }

    unsigned node0 = blockIdx.x * 128u;
    unsigned lane8 = tid & 7;           // channel lane within node
    const uint4* xw = (const uint4*)g_xw;
    const int4* adj4 = (const int4*)g_adj;
    const float4* b14 = (const float4*)b1;
    float4 bb0 = __ldg(&b14[lane8 * 2]);
    float4 bb1 = __ldg(&b14[lane8 * 2 + 1]);

    // Phase 1: 4 passes x 32 nodes (256 threads / 8 lanes)
#pragma unroll 1
    for (int pass = 0; pass < 4; pass++) {
        unsigned slot = pass * 32 + (tid >> 3);      // local node slot 0..127
        unsigned node = node0 + slot;
        if (node < NN) {
            float acc[8];
            {
                uint4 sv = __ldg(&xw[node * 8u + lane8]);
                const __half2* hp = (const __half2*)&sv;
#pragma unroll
                for (int j = 0; j < 4; j++) {
                    float2 f = __half22float2(hp[j]);
                    acc[2 * j] = f.x;
                    acc[2 * j + 1] = f.y;
                }
            }
            unsigned s = node * ELLW;
            unsigned e = s + (unsigned)__ldg(&g_cnt[node]);
            unsigned k = s;
            for (; k + 8 <= e; k += 8) {
                int4 i0 = __ldg(&adj4[k >> 2]);
                int4 i1 = __ldg(&adj4[(k >> 2) + 1]);
                uint4 u0 = __ldg(&xw[(unsigned)i0.x * 8u + lane8]);
                uint4 u1 = __ldg(&xw[(unsigned)i0.y * 8u + lane8]);
                uint4 u2 = __ldg(&xw[(unsigned)i0.z * 8u + lane8]);
                uint4 u3 = __ldg(&xw[(unsigned)i0.w * 8u + lane8]);
                uint4 u4 = __ldg(&xw[(unsigned)i1.x * 8u + lane8]);
                uint4 u5 = __ldg(&xw[(unsigned)i1.y * 8u + lane8]);
                uint4 u6 = __ldg(&xw[(unsigned)i1.z * 8u + lane8]);
                uint4 u7 = __ldg(&xw[(unsigned)i1.w * 8u + lane8]);
                acc_oct(acc, u0, u1, u2, u3, u4, u5, u6, u7);
            }
            for (; k + 2 <= e; k += 2) {
                int r0 = __ldg(&g_adj[k]);
                int r1 = __ldg(&g_adj[k + 1]);
                uint4 u0 = __ldg(&xw[(unsigned)r0 * 8u + lane8]);
                uint4 u1 = __ldg(&xw[(unsigned)r1 * 8u + lane8]);
                acc_pair(acc, u0, u1);
            }
            if (k < e) {
                int r = __ldg(&g_adj[k]);
                uint4 u = __ldg(&xw[(unsigned)r * 8u + lane8]);
                acc_one(acc, u);
            }
            float di = __ldg(&g_dinv[node]);
            __half2 o[4];
            o[0] = __floats2half2_rn(fmaxf(fmaf(di, acc[0], bb0.x), 0.f),
                                     fmaxf(fmaf(di, acc[1], bb0.y), 0.f));
            o[1] = __floats2half2_rn(fmaxf(fmaf(di, acc[2], bb0.z), 0.f),
                                     fmaxf(fmaf(di, acc[3], bb0.w), 0.f));
            o[2] = __floats2half2_rn(fmaxf(fmaf(di, acc[4], bb1.x), 0.f),
                                     fmaxf(fmaf(di, acc[5], bb1.y), 0.f));
            o[3] = __floats2half2_rn(fmaxf(fmaf(di, acc[6], bb1.z), 0.f),
                                     fmaxf(fmaf(di, acc[7], bb1.w), 0.f));
            *(uint4*)&H1s[slot * SPH + lane8 * 8] = *(const uint4*)o;
        } else {
            // keep smem defined for the HMMA phase (outputs unused but avoid NaN reads)
            uint4 z = make_uint4(0, 0, 0, 0);
            *(uint4*)&H1s[slot * SPH + lane8 * 8] = z;
        }
    }
    __syncthreads();

    // Phase 2: HMMA gemm2 from smem h1 tile
    int warp = tid >> 5, lane = tid & 31;
    int g = lane >> 2, t = lane & 3;
    int slot0 = warp * 16 + g;                    // local rows slot0, slot0+8
    int row0 = (int)node0 + slot0;
    const __half* H0 = &H1s[slot0 * SPH];
    const __half* H1 = &H1s[(slot0 + 8) * SPH];

    float d[5][4];
#pragma unroll
    for (int j = 0; j < 5; j++)
#pragma unroll
        for (int q = 0; q < 4; q++) d[j][q] = 0.f;

#pragma unroll
    for (int kk = 0; kk < 4; kk++) {
        int kb = kk * 16 + t * 2;
        unsigned a[4];
        a[0] = *(const unsigned*)(H0 + kb);
        a[1] = *(const unsigned*)(H1 + kb);
        a[2] = *(const unsigned*)(H0 + kb + 8);
        a[3] = *(const unsigned*)(H1 + kb + 8);
#pragma unroll
        for (int j = 0; j < 5; j++) {
            int n = j * 8 + g;
            const __half* ph = &Wh[n * SP2 + kk * 16 + t * 2];
            const __half* pl = &Wl[n * SP2 + kk * 16 + t * 2];
            unsigned bh0 = *(const unsigned*)ph;
            unsigned bh1 = *(const unsigned*)(ph + 8);
            unsigned bl0 = *(const unsigned*)pl;
            unsigned bl1 = *(const unsigned*)(pl + 8);
            mma16816(d[j], a, bh0, bh1);
            mma16816(d[j], a, bl0, bl1);
        }
    }

    float di0 = (row0 < NN) ? __ldg(&g_dinv[row0]) : 0.f;
    float di1 = (row0 + 8 < NN) ? __ldg(&g_dinv[row0 + 8]) : 0.f;
#pragma unroll
    for (int j = 0; j < 5; j++) {
        int c0 = j * 8 + t * 2;
        if (row0 < NN) {
            __half2 p = __floats2half2_rn(di0 * d[j][0], di0 * d[j][1]);
            *(unsigned*)&g_h2[(unsigned)row0 * 40 + c0] = *(unsigned*)&p;
        }
        if (row0 + 8 < NN) {
            __half2 p = __floats2half2_rn(di1 * d[j][2], di1 * d[j][3]);
            *(unsigned*)&g_h2[(unsigned)(row0 + 8) * 40 + c0] = *(unsigned*)&p;
        }
    }
}

// ---------------- agg2: out = dinv[c]*(sum_r scaled[r] + scaled[c]) + b2 ----------------
// 5 lanes/node (6 nodes/warp); sequential node order (locality-preserving).
__global__ void agg2_kernel(const float* __restrict__ b2, float* __restrict__ out) {
    unsigned gtid = blockIdx.x * blockDim.x + threadIdx.x;
    unsigned wid = gtid >> 5;
    unsigned lane = gtid & 31;
    unsigned g = lane / 5;
    unsigned sub = lane - g * 5;
    if (g >= 6) return;
    unsigned node = wid * 6 + g;
    if (node >= NN) return;
    const uint4* hh = (const uint4*)g_h2;

    float acc[8];
    {
        uint4 sv = __ldg(&hh[node * 5u + sub]);
        const __half2* hp = (const __half2*)&sv;
#pragma unroll
        for (int j = 0; j < 4; j++) {
            float2 f = __half22float2(hp[j]);
            acc[2 * j] = f.x;
            acc[2 * j + 1] = f.y;
        }
    }

    unsigned s = node * ELLW;
    unsigned e = s + (unsigned)__ldg(&g_cnt[node]);
    unsigned k = s;
    const int4* adj4 = (const int4*)g_adj;
    for (; k + 8 <= e; k += 8) {
        int4 i0 = __ldg(&adj4[k >> 2]);
        int4 i1 = __ldg(&adj4[(k >> 2) + 1]);
        uint4 u0 = __ldg(&hh[(unsigned)i0.x * 5u + sub]);
        uint4 u1 = __ldg(&hh[(unsigned)i0.y * 5u + sub]);
        uint4 u2 = __ldg(&hh[(unsigned)i0.z * 5u + sub]);
        uint4 u3 = __ldg(&hh[(unsigned)i0.w * 5u + sub]);
        uint4 u4 = __ldg(&hh[(unsigned)i1.x * 5u + sub]);
        uint4 u5 = __ldg(&hh[(unsigned)i1.y * 5u + sub]);
        uint4 u6 = __ldg(&hh[(unsigned)i1.z * 5u + sub]);
        uint4 u7 = __ldg(&hh[(unsigned)i1.w * 5u + sub]);
        acc_oct(acc, u0, u1, u2, u3, u4, u5, u6, u7);
    }
    for (; k + 2 <= e; k += 2) {
        int r0 = __ldg(&g_adj[k]);
        int r1 = __ldg(&g_adj[k + 1]);
        uint4 u0 = __ldg(&hh[(unsigned)r0 * 5u + sub]);
        uint4 u1 = __ldg(&hh[(unsigned)r1 * 5u + sub]);
        acc_pair(acc, u0, u1);
    }
    if (k < e) {
        int r = __ldg(&g_adj[k]);
        uint4 u = __ldg(&hh[(unsigned)r * 5u + sub]);
        acc_one(acc, u);
    }

    float di = __ldg(&g_dinv[node]);
    const float4* b24 = (const float4*)b2;
    float4 bb0 = __ldg(&b24[sub * 2]);
    float4 bb1 = __ldg(&b24[sub * 2 + 1]);
    float4 o0, o1;
    o0.x = fmaf(di, acc[0], bb0.x);
    o0.y = fmaf(di, acc[1], bb0.y);
    o0.z = fmaf(di, acc[2], bb0.z);
    o0.w = fmaf(di, acc[3], bb0.w);
    o1.x = fmaf(di, acc[4], bb1.x);
    o1.y = fmaf(di, acc[5], bb1.y);
    o1.z = fmaf(di, acc[6], bb1.z);
    o1.w = fmaf(di, acc[7], bb1.w);
    float4* dst = (float4*)&out[(unsigned)node * 40 + sub * 8];
    dst[0] = o0;
    dst[1] = o1;
}

// ---------------- launch ----------------
extern "C" void kernel_launch(void* const* d_in, const int* in_sizes, int n_in,
                              void* d_out, int out_size) {
    const float* x  = (const float*)d_in[0];
    const void*  ei = d_in[1];
    const float* W1 = (const float*)d_in[2];
    const float* b1 = (const float*)d_in[3];
    const float* W2 = (const float*)d_in[4];
    const float* b2 = (const float*)d_in[5];
    float* out = (float*)d_out;

    init_kernel<<<(NN + 255) / 256, 256>>>(ei);
    fused_g1_scatter_kernel<<<G1_BLOCKS + SC_BLOCKS, 256>>>(x, W1, ei);
    dinv_scale_kernel<<<(NN * 8 + 255) / 256, 256>>>();
    agg1_gemm2_kernel<<<G1_BLOCKS, 256>>>(b1, W2);
    agg2_kernel<<<(NN + 47) / 48, 256>>>(b2, out);
}